// round 3
// baseline (speedup 1.0000x reference)
#include <cuda_runtime.h>
#include <math.h>

#define S 1024
#define D 1024
#define H 16
#define HD 64
#define NL 6
#define DFF 4096
#define EPS 1.1920929e-07f

// ---------------- scratch (no allocations allowed) ----------------
__device__ float g_x [S*D];
__device__ float g_x0[S*D];
__device__ float g_xl[S*D];
__device__ float g_xn[S*D];
__device__ float g_q [S*D];
__device__ float g_k [S*D];
__device__ float g_v [S*D];
__device__ float g_v1[S*D];
__device__ float g_y [S*D];
__device__ float g_h [S*DFF];
__device__ unsigned char g_mask[S*S];
__device__ int   g_cpad[S+1];
__device__ float g_cos[S*32];
__device__ float g_sin[S*32];

// ---------------- prefix sum of (levels==0) ----------------
__global__ void scan_kernel(const int* __restrict__ levels, int* __restrict__ cpad) {
    __shared__ int sh[S];
    int t = threadIdx.x;
    sh[t] = (levels[t] == 0) ? 1 : 0;
    __syncthreads();
    for (int off = 1; off < S; off <<= 1) {
        int add = (t >= off) ? sh[t - off] : 0;
        __syncthreads();
        sh[t] += add;
        __syncthreads();
    }
    cpad[t + 1] = sh[t];
    if (t == 0) cpad[0] = 0;
}

// ---------------- markov mask ----------------
__global__ void mask_kernel(const int* __restrict__ levels, const int* __restrict__ sidx,
                            const int* __restrict__ cpad, unsigned char* __restrict__ mk) {
    int idx = blockIdx.x * 256 + threadIdx.x;
    int i = idx >> 10, j = idx & 1023;
    bool causal = (i >= j);
    bool same   = (sidx[i] == sidx[j]);
    int  cnt    = cpad[i] - cpad[j + 1];
    bool markov = (levels[j] == 0) && (cnt > 0);
    mk[idx] = (causal && same && !markov) ? 1 : 0;
}

// ---------------- rope tables ----------------
__global__ void ropetab_kernel(float* __restrict__ ct, float* __restrict__ st) {
    int t = blockIdx.x, l = threadIdx.x;
    double inv = pow(10000.0, -(double)(2 * l) / (double)HD);
    double fr  = (double)t * inv;
    ct[t * 32 + l] = (float)cos(fr);
    st[t * 32 + l] = (float)sin(fr);
}

// ---------------- rms over rows of width D (out2 optional copy) ----------------
__global__ __launch_bounds__(256) void rms_dual_kernel(const float* __restrict__ in,
                                                       float* __restrict__ out1,
                                                       float* __restrict__ out2) {
    int row = blockIdx.x, tid = threadIdx.x;
    const float* p = in + row * D;
    float s = 0.f;
    for (int c = tid; c < D; c += 256) { float v = p[c]; s += v * v; }
    __shared__ float red[8];
    #pragma unroll
    for (int o = 16; o; o >>= 1) s += __shfl_xor_sync(0xffffffffu, s, o);
    if ((tid & 31) == 0) red[tid >> 5] = s;
    __syncthreads();
    if (tid == 0) {
        float t2 = 0.f;
        #pragma unroll
        for (int w = 0; w < 8; w++) t2 += red[w];
        red[0] = t2;
    }
    __syncthreads();
    float scale = rsqrtf(red[0] * (1.0f / D) + EPS);
    for (int c = tid; c < D; c += 256) {
        float v = p[c] * scale;
        out1[row * D + c] = v;
        if (out2) out2[row * D + c] = p[c] * scale;
    }
}

// ---------------- xl = l0*x + l1*x0 ; xn = rms(xl) ----------------
__global__ __launch_bounds__(256) void prelayer_kernel(const float* __restrict__ x,
                                                       const float* __restrict__ x0,
                                                       const float* __restrict__ lambdas, int layer,
                                                       float* __restrict__ xl, float* __restrict__ xn) {
    int row = blockIdx.x, tid = threadIdx.x;
    float l0 = lambdas[2 * layer], l1 = lambdas[2 * layer + 1];
    float s = 0.f;
    for (int c = tid; c < D; c += 256) {
        float v = l0 * x[row * D + c] + l1 * x0[row * D + c];
        xl[row * D + c] = v;
        s += v * v;
    }
    __shared__ float red[8];
    #pragma unroll
    for (int o = 16; o; o >>= 1) s += __shfl_xor_sync(0xffffffffu, s, o);
    if ((tid & 31) == 0) red[tid >> 5] = s;
    __syncthreads();
    if (tid == 0) {
        float t2 = 0.f;
        #pragma unroll
        for (int w = 0; w < 8; w++) t2 += red[w];
        red[0] = t2;
    }
    __syncthreads();
    float scale = rsqrtf(red[0] * (1.0f / D) + EPS);
    for (int c = tid; c < D; c += 256) xn[row * D + c] = xl[row * D + c] * scale;
}

// ---------------- GEMM: C[M,N] = A[M,K] @ B[N,K]^T, epilogue via template ----------------
// EPI 0: none, 1: C = Res + acc, 2: C = relu(acc)^2
// blockIdx.z selects (B0,C0)/(B1,C1)/(B2,C2) for fused QKV.
template <int EPI>
__global__ __launch_bounds__(256) void gemm64_kernel(
    const float* __restrict__ A,
    const float* __restrict__ B0, const float* __restrict__ B1, const float* __restrict__ B2,
    float* __restrict__ C0, float* __restrict__ C1, float* __restrict__ C2,
    const float* __restrict__ Res, int M, int N, int K) {
    const float* B = B0; float* C = C0;
    if (blockIdx.z == 1) { B = B1; C = C1; }
    else if (blockIdx.z == 2) { B = B2; C = C2; }

    __shared__ float As[16][68];
    __shared__ float Bs[16][68];
    int tid = threadIdx.x;
    int row0 = blockIdx.y * 64, col0 = blockIdx.x * 64;
    int lm = tid >> 2;           // 0..63
    int lk = (tid & 3) * 4;      // 0,4,8,12
    int ty = tid >> 4, tx = tid & 15;
    const float* Ag = A + (size_t)(row0 + lm) * K + lk;
    const float* Bg = B + (size_t)(col0 + lm) * K + lk;
    float acc[4][4] = {};

    for (int k0 = 0; k0 < K; k0 += 16) {
        float4 a4 = *(const float4*)(Ag + k0);
        float4 b4 = *(const float4*)(Bg + k0);
        As[lk + 0][lm] = a4.x; As[lk + 1][lm] = a4.y; As[lk + 2][lm] = a4.z; As[lk + 3][lm] = a4.w;
        Bs[lk + 0][lm] = b4.x; Bs[lk + 1][lm] = b4.y; Bs[lk + 2][lm] = b4.z; Bs[lk + 3][lm] = b4.w;
        __syncthreads();
        #pragma unroll
        for (int kk = 0; kk < 16; kk++) {
            float4 rav = *(const float4*)&As[kk][ty * 4];
            float4 rbv = *(const float4*)&Bs[kk][tx * 4];
            float ra[4] = { rav.x, rav.y, rav.z, rav.w };
            float rb[4] = { rbv.x, rbv.y, rbv.z, rbv.w };
            #pragma unroll
            for (int i = 0; i < 4; i++)
                #pragma unroll
                for (int j = 0; j < 4; j++)
                    acc[i][j] += ra[i] * rb[j];
        }
        __syncthreads();
    }

    #pragma unroll
    for (int i = 0; i < 4; i++) {
        int r = row0 + ty * 4 + i;
        float v[4] = { acc[i][0], acc[i][1], acc[i][2], acc[i][3] };
        if (EPI == 1) {
            float4 rr = *(const float4*)&Res[(size_t)r * N + col0 + tx * 4];
            v[0] += rr.x; v[1] += rr.y; v[2] += rr.z; v[3] += rr.w;
        }
        if (EPI == 2) {
            #pragma unroll
            for (int j = 0; j < 4; j++) { float t = fmaxf(v[j], 0.f); v[j] = t * t; }
        }
        float4 w = make_float4(v[0], v[1], v[2], v[3]);
        *(float4*)&C[(size_t)r * N + col0 + tx * 4] = w;
    }
}

// ---------------- per-head rms + rope on q,k ; value mixing ----------------
__global__ __launch_bounds__(128) void qkvprep_kernel(float* __restrict__ Q, float* __restrict__ Kt,
                                                      float* __restrict__ V, float* __restrict__ V1,
                                                      const float* __restrict__ lamb, int layer,
                                                      const float* __restrict__ ctab,
                                                      const float* __restrict__ stab) {
    int t = blockIdx.x;
    int h = blockIdx.y * 4 + (threadIdx.x >> 5);
    int lane = threadIdx.x & 31;
    int base = t * D + h * HD;
    float c  = ctab[t * 32 + lane];
    float sn = stab[t * 32 + lane];

    // q
    float a = Q[base + lane], b = Q[base + 32 + lane];
    float s = a * a + b * b;
    #pragma unroll
    for (int o = 16; o; o >>= 1) s += __shfl_xor_sync(0xffffffffu, s, o);
    float r = rsqrtf(s * (1.0f / HD) + EPS);
    a *= r; b *= r;
    Q[base + lane]      =  a * c + b * sn;
    Q[base + 32 + lane] = -a * sn + b * c;

    // k
    a = Kt[base + lane]; b = Kt[base + 32 + lane];
    s = a * a + b * b;
    #pragma unroll
    for (int o = 16; o; o >>= 1) s += __shfl_xor_sync(0xffffffffu, s, o);
    r = rsqrtf(s * (1.0f / HD) + EPS);
    a *= r; b *= r;
    Kt[base + lane]      =  a * c + b * sn;
    Kt[base + 32 + lane] = -a * sn + b * c;

    // v mixing with layer-0 v
    float lm = lamb[layer];
    float v0 = V[base + lane], v1 = V[base + 32 + lane];
    if (layer == 0) { V1[base + lane] = v0; V1[base + 32 + lane] = v1; }
    float w0 = V1[base + lane], w1 = V1[base + 32 + lane];
    V[base + lane]      = (1.f - lm) * v0 + lm * w0;
    V[base + 32 + lane] = (1.f - lm) * v1 + lm * w1;
}

// ---------------- flash attention with markov mask ----------------
// 32 queries/block, 64-key tiles, 128 threads (16x8 of 4x4 micro-tiles).
__global__ __launch_bounds__(128) void attn_kernel(const float* __restrict__ Q,
                                                   const float* __restrict__ Kg,
                                                   const float* __restrict__ Vg,
                                                   float* __restrict__ Y,
                                                   const unsigned char* __restrict__ mk) {
    const int h  = blockIdx.y;
    const int q0 = blockIdx.x * 32;
    const int tid = threadIdx.x;
    const int ty = tid >> 4, tx = tid & 15;   // ty 0..7 (query rows), tx 0..15 (cols)

    __shared__ float qs[64][33];   // [d][q]
    __shared__ float kp[64][65];   // union: K tile [d][k] -> P tile [k][q]
    __shared__ float vs[64][64];   // [k][d]

    // load Q transposed
    for (int i = tid; i < 512; i += 128) {
        int qr = i >> 4, dq = i & 15;
        float4 a = *(const float4*)(Q + (size_t)(q0 + qr) * D + h * HD + dq * 4);
        qs[dq * 4 + 0][qr] = a.x; qs[dq * 4 + 1][qr] = a.y;
        qs[dq * 4 + 2][qr] = a.z; qs[dq * 4 + 3][qr] = a.w;
    }

    float o[4][4] = {};
    float m[4], l[4];
    #pragma unroll
    for (int i = 0; i < 4; i++) { m[i] = -1e30f; l[i] = 0.f; }

    const int ktiles = q0 / 64 + 1;   // causal: skip tiles fully above diagonal
    for (int kt = 0; kt < ktiles; kt++) {
        const int k0 = kt * 64;
        __syncthreads();   // protect kp reuse + q tile on first iter
        for (int i = tid; i < 1024; i += 128) {
            int kr = i >> 4, dq = i & 15;
            float4 a = *(const float4*)(Kg + (size_t)(k0 + kr) * D + h * HD + dq * 4);
            kp[dq * 4 + 0][kr] = a.x; kp[dq * 4 + 1][kr] = a.y;
            kp[dq * 4 + 2][kr] = a.z; kp[dq * 4 + 3][kr] = a.w;
            float4 b = *(const float4*)(Vg + (size_t)(k0 + kr) * D + h * HD + dq * 4);
            *(float4*)&vs[kr][dq * 4] = b;
        }
        __syncthreads();

        // scores S = Q K^T
        float s[4][4] = {};
        #pragma unroll 8
        for (int kk = 0; kk < 64; kk++) {
            float ra[4], rb[4];
            #pragma unroll
            for (int i = 0; i < 4; i++) ra[i] = qs[kk][ty * 4 + i];
            #pragma unroll
            for (int j = 0; j < 4; j++) rb[j] = kp[kk][tx * 4 + j];
            #pragma unroll
            for (int i = 0; i < 4; i++)
                #pragma unroll
                for (int j = 0; j < 4; j++)
                    s[i][j] += ra[i] * rb[j];
        }

        // mask + scale
        #pragma unroll
        for (int i = 0; i < 4; i++) {
            int qi = q0 + ty * 4 + i;
            const unsigned char* mrow = mk + (size_t)qi * S + k0 + tx * 4;
            #pragma unroll
            for (int j = 0; j < 4; j++)
                s[i][j] = mrow[j] ? s[i][j] * 0.125f : -1e30f;
        }

        // online softmax (row group = 16 consecutive lanes)
        #pragma unroll
        for (int i = 0; i < 4; i++) {
            float tm = fmaxf(fmaxf(s[i][0], s[i][1]), fmaxf(s[i][2], s[i][3]));
            #pragma unroll
            for (int off = 1; off < 16; off <<= 1)
                tm = fmaxf(tm, __shfl_xor_sync(0xffffffffu, tm, off));
            float nm = fmaxf(m[i], tm);
            float f  = __expf(m[i] - nm);
            float rs = 0.f;
            #pragma unroll
            for (int j = 0; j < 4; j++) { s[i][j] = __expf(s[i][j] - nm); rs += s[i][j]; }
            #pragma unroll
            for (int off = 1; off < 16; off <<= 1)
                rs += __shfl_xor_sync(0xffffffffu, rs, off);
            l[i] = l[i] * f + rs;
            m[i] = nm;
            #pragma unroll
            for (int j = 0; j < 4; j++) o[i][j] *= f;
        }

        __syncthreads();   // done reading kp as K
        #pragma unroll
        for (int i = 0; i < 4; i++)
            #pragma unroll
            for (int j = 0; j < 4; j++)
                kp[tx * 4 + j][ty * 4 + i] = s[i][j];   // P transposed [k][q]
        __syncthreads();

        // O += P^T V
        #pragma unroll 8
        for (int kk = 0; kk < 64; kk++) {
            float ra[4], rb[4];
            #pragma unroll
            for (int i = 0; i < 4; i++) ra[i] = kp[kk][ty * 4 + i];
            #pragma unroll
            for (int j = 0; j < 4; j++) rb[j] = vs[kk][tx * 4 + j];
            #pragma unroll
            for (int i = 0; i < 4; i++)
                #pragma unroll
                for (int j = 0; j < 4; j++)
                    o[i][j] += ra[i] * rb[j];
        }
    }

    #pragma unroll
    for (int i = 0; i < 4; i++) {
        int t = q0 + ty * 4 + i;
        float inv = 1.f / l[i];
        #pragma unroll
        for (int j = 0; j < 4; j++)
            Y[(size_t)t * D + h * HD + tx * 4 + j] = o[i][j] * inv;
    }
}

// ---------------- host ----------------
extern "C" void kernel_launch(void* const* d_in, const int* in_sizes, int n_in,
                              void* d_out, int out_size) {
    const float* x       = (const float*)d_in[0];
    const float* Wq      = (const float*)d_in[1];
    const float* Wk      = (const float*)d_in[2];
    const float* Wv      = (const float*)d_in[3];
    const float* Wo      = (const float*)d_in[4];
    const float* lamb    = (const float*)d_in[5];
    const float* lambdas = (const float*)d_in[6];
    const float* Wfc     = (const float*)d_in[7];
    const float* Wp      = (const float*)d_in[8];
    const int*   levels  = (const int*)d_in[9];
    const int*   sidx    = (const int*)d_in[10];
    float* out = (float*)d_out;

    float *px, *px0, *pxl, *pxn, *pq, *pk, *pv, *pv1, *py, *ph, *pcos, *psin;
    unsigned char* pmask; int* pcpad;
    cudaGetSymbolAddress((void**)&px,   g_x);
    cudaGetSymbolAddress((void**)&px0,  g_x0);
    cudaGetSymbolAddress((void**)&pxl,  g_xl);
    cudaGetSymbolAddress((void**)&pxn,  g_xn);
    cudaGetSymbolAddress((void**)&pq,   g_q);
    cudaGetSymbolAddress((void**)&pk,   g_k);
    cudaGetSymbolAddress((void**)&pv,   g_v);
    cudaGetSymbolAddress((void**)&pv1,  g_v1);
    cudaGetSymbolAddress((void**)&py,   g_y);
    cudaGetSymbolAddress((void**)&ph,   g_h);
    cudaGetSymbolAddress((void**)&pmask, g_mask);
    cudaGetSymbolAddress((void**)&pcpad, g_cpad);
    cudaGetSymbolAddress((void**)&pcos, g_cos);
    cudaGetSymbolAddress((void**)&psin, g_sin);

    scan_kernel<<<1, S>>>(levels, pcpad);
    mask_kernel<<<(S * S) / 256, 256>>>(levels, sidx, pcpad, pmask);
    ropetab_kernel<<<S, 32>>>(pcos, psin);
    rms_dual_kernel<<<S, 256>>>(x, px, px0);

    for (int i = 0; i < NL; i++) {
        prelayer_kernel<<<S, 256>>>(px, px0, lambdas, i, pxl, pxn);

        // fused QKV projections
        gemm64_kernel<0><<<dim3(D / 64, S / 64, 3), 256>>>(
            pxn, Wq + (size_t)i * D * D, Wk + (size_t)i * D * D, Wv + (size_t)i * D * D,
            pq, pk, pv, nullptr, S, D, D);

        qkvprep_kernel<<<dim3(S, 4), 128>>>(pq, pk, pv, pv1, lamb, i, pcos, psin);

        attn_kernel<<<dim3(S / 32, H), 128>>>(pq, pk, pv, py, pmask);

        // x = xl + y @ Wo^T
        gemm64_kernel<1><<<dim3(D / 64, S / 64, 1), 256>>>(
            py, Wo + (size_t)i * D * D, nullptr, nullptr,
            px, nullptr, nullptr, pxl, S, D, D);

        // h = relu(rms(x) @ Wfc^T)^2
        rms_dual_kernel<<<S, 256>>>(px, pxn, nullptr);
        gemm64_kernel<2><<<dim3(DFF / 64, S / 64, 1), 256>>>(
            pxn, Wfc + (size_t)i * DFF * D, nullptr, nullptr,
            ph, nullptr, nullptr, nullptr, S, DFF, D);

        // x = x + h @ Wp^T
        gemm64_kernel<1><<<dim3(D / 64, S / 64, 1), 256>>>(
            ph, Wp + (size_t)i * D * DFF, nullptr, nullptr,
            px, nullptr, nullptr, px, S, D, DFF);
    }

    rms_dual_kernel<<<S, 256>>>(px, out, nullptr);
}